// round 3
// baseline (speedup 1.0000x reference)
#include <cuda_runtime.h>
#include <math.h>

// ---------------------------------------------------------------------------
// Problem constants (fixed shapes from setup_inputs):
//   B=8, Nc=1024, Nt=1024, Dx=3, Dy=32, H=128
// inputs order: xc, yc, xt, W0, b0, W1, b1, W2, b2, W3, b3   (all float32)
// output: (B, Nt, Dy) float32
// ---------------------------------------------------------------------------

#define B_SZ 8
#define NC 1024
#define NT 1024
#define HID 128
#define DY 32

// Per-target precomputed "query" vector (7 used + 1 pad), already scaled by log2(e):
//   q[0..2] =  2*sig_d*xt_d*L2E
//   q[3..5] = -sig_d*L2E
//   q[6]    = -(sum_d sig_d*xt_d^2)*L2E
// so   log2-logit = q6 + sum q[d]*x_d + sum q[3+d]*x_d^2
__device__ float g_q[B_SZ * NT * 8];

// ======================= Kernel 1: MLP -> sigma -> q =======================
// 256 blocks x 256 threads; each block handles 32 points.
// Dynamic smem holds W1, W2 (64KB each) + small weights + activations.

#define TPB1 256
#define oW1 0
#define oW2 16384
#define oW0 32768   /* 3*128 = 384 */
#define oW3 33152   /* 128*3 = 384 */
#define ob0 33536
#define ob1 33664
#define ob2 33792
#define ob3 33920   /* 3 (pad 16) */
#define oxt 33936   /* 32*3 = 96 (pad 128) */
#define ohA 34064   /* 4*128*8 = 4096 */
#define ohB 38160   /* 4096 */
#define oso 42256   /* 4*8*3 = 96 (pad 128) */
#define SMEM1_FLOATS 42384

__device__ __forceinline__ void cp4(float* dst, const float* src, int n4, int tid) {
    const float4* s4 = (const float4*)src;
    float4* d4 = (float4*)dst;
    for (int i = tid; i < n4; i += TPB1) d4[i] = s4[i];
}

// hidden layer: out[u] = relu(b[u] + sum_k in[k]*W[k][u]); thread owns units u0,u0+1
// for 8 points of its group.
__device__ __forceinline__ void hidden_layer(float* s, int oin, int oout,
                                             int oW, int ob, int g, int j) {
    int u0 = j * 2;
    float acc0[8], acc1[8];
    float bb0 = s[ob + u0], bb1 = s[ob + u0 + 1];
#pragma unroll
    for (int q = 0; q < 8; ++q) { acc0[q] = bb0; acc1[q] = bb1; }
    const float4* in4 = (const float4*)&s[oin + g * 1024];
    const float2* Wp  = (const float2*)&s[oW];
#pragma unroll 4
    for (int k = 0; k < 128; ++k) {
        float4 h0 = in4[k * 2];
        float4 h1 = in4[k * 2 + 1];
        float2 w  = Wp[k * 64 + j];
        acc0[0] = fmaf(h0.x, w.x, acc0[0]); acc0[1] = fmaf(h0.y, w.x, acc0[1]);
        acc0[2] = fmaf(h0.z, w.x, acc0[2]); acc0[3] = fmaf(h0.w, w.x, acc0[3]);
        acc0[4] = fmaf(h1.x, w.x, acc0[4]); acc0[5] = fmaf(h1.y, w.x, acc0[5]);
        acc0[6] = fmaf(h1.z, w.x, acc0[6]); acc0[7] = fmaf(h1.w, w.x, acc0[7]);
        acc1[0] = fmaf(h0.x, w.y, acc1[0]); acc1[1] = fmaf(h0.y, w.y, acc1[1]);
        acc1[2] = fmaf(h0.z, w.y, acc1[2]); acc1[3] = fmaf(h0.w, w.y, acc1[3]);
        acc1[4] = fmaf(h1.x, w.y, acc1[4]); acc1[5] = fmaf(h1.y, w.y, acc1[5]);
        acc1[6] = fmaf(h1.z, w.y, acc1[6]); acc1[7] = fmaf(h1.w, w.y, acc1[7]);
    }
    float4* od = (float4*)&s[oout + (g * 128 + u0) * 8];
    od[0] = make_float4(fmaxf(acc0[0], 0.f), fmaxf(acc0[1], 0.f), fmaxf(acc0[2], 0.f), fmaxf(acc0[3], 0.f));
    od[1] = make_float4(fmaxf(acc0[4], 0.f), fmaxf(acc0[5], 0.f), fmaxf(acc0[6], 0.f), fmaxf(acc0[7], 0.f));
    od[2] = make_float4(fmaxf(acc1[0], 0.f), fmaxf(acc1[1], 0.f), fmaxf(acc1[2], 0.f), fmaxf(acc1[3], 0.f));
    od[3] = make_float4(fmaxf(acc1[4], 0.f), fmaxf(acc1[5], 0.f), fmaxf(acc1[6], 0.f), fmaxf(acc1[7], 0.f));
}

__global__ void __launch_bounds__(TPB1, 1)
mlp_kernel(const float* __restrict__ xt,
           const float* __restrict__ W0, const float* __restrict__ b0,
           const float* __restrict__ W1, const float* __restrict__ b1,
           const float* __restrict__ W2, const float* __restrict__ b2,
           const float* __restrict__ W3, const float* __restrict__ b3) {
    extern __shared__ float s[];
    int tid = threadIdx.x;

    cp4(&s[oW1], W1, 4096, tid);
    cp4(&s[oW2], W2, 4096, tid);
    cp4(&s[oW0], W0, 96, tid);
    cp4(&s[oW3], W3, 96, tid);
    cp4(&s[ob0], b0, 32, tid);
    cp4(&s[ob1], b1, 32, tid);
    cp4(&s[ob2], b2, 32, tid);
    if (tid < 3) s[ob3 + tid] = b3[tid];

    int pbase = blockIdx.x * 32;
    if (tid < 96) s[oxt + tid] = xt[pbase * 3 + tid];
    __syncthreads();

    int g = tid >> 6;        // 4 groups of 8 points
    int j = tid & 63;        // unit pair index
    int u0 = j * 2;

    // ---- layer 0: 3 -> 128 ----
    {
        float a0[8], a1[8];
        float bb0 = s[ob0 + u0], bb1 = s[ob0 + u0 + 1];
        float w00 = s[oW0 + u0],       w01 = s[oW0 + u0 + 1];
        float w10 = s[oW0 + 128 + u0], w11 = s[oW0 + 128 + u0 + 1];
        float w20 = s[oW0 + 256 + u0], w21 = s[oW0 + 256 + u0 + 1];
#pragma unroll
        for (int q = 0; q < 8; ++q) {
            int lp = g * 8 + q;
            float x0 = s[oxt + lp * 3 + 0];
            float x1 = s[oxt + lp * 3 + 1];
            float x2 = s[oxt + lp * 3 + 2];
            a0[q] = fmaxf(fmaf(x2, w20, fmaf(x1, w10, fmaf(x0, w00, bb0))), 0.f);
            a1[q] = fmaxf(fmaf(x2, w21, fmaf(x1, w11, fmaf(x0, w01, bb1))), 0.f);
        }
        float4* Adst = (float4*)&s[ohA + (g * 128 + u0) * 8];
        Adst[0] = make_float4(a0[0], a0[1], a0[2], a0[3]);
        Adst[1] = make_float4(a0[4], a0[5], a0[6], a0[7]);
        Adst[2] = make_float4(a1[0], a1[1], a1[2], a1[3]);
        Adst[3] = make_float4(a1[4], a1[5], a1[6], a1[7]);
    }
    __syncthreads();

    hidden_layer(s, ohA, ohB, oW1, ob1, g, j);   // layer 1
    __syncthreads();
    hidden_layer(s, ohB, ohA, oW2, ob2, g, j);   // layer 2
    __syncthreads();

    // ---- output layer: 128 -> 3 (24 active threads per group) ----
    if (j < 24) {
        int qq = j / 3, d = j - qq * 3;
        float acc = s[ob3 + d];
        const float* hin = &s[ohA + g * 1024];
#pragma unroll 8
        for (int k = 0; k < 128; ++k)
            acc = fmaf(hin[k * 8 + qq], s[oW3 + k * 3 + d], acc);
        s[oso + (g * 8 + qq) * 3 + d] = acc;
    }
    __syncthreads();

    // ---- epilogue: sigma = exp(o), build q-vector ----
    if (tid < 32) {
        int lp = tid;
        float o0 = s[oso + lp * 3 + 0];
        float o1 = s[oso + lp * 3 + 1];
        float o2 = s[oso + lp * 3 + 2];
        float s0 = expf(o0), s1 = expf(o1), s2 = expf(o2);
        float x0 = s[oxt + lp * 3 + 0];
        float x1 = s[oxt + lp * 3 + 1];
        float x2 = s[oxt + lp * 3 + 2];
        const float L2E = 1.44269504088896340736f;
        float c6 = -(s0 * x0 * x0 + s1 * x1 * x1 + s2 * x2 * x2) * L2E;
        float4* qd = (float4*)&g_q[(pbase + lp) * 8];
        qd[0] = make_float4(2.f * s0 * x0 * L2E, 2.f * s1 * x1 * L2E,
                            2.f * s2 * x2 * L2E, -s0 * L2E);
        qd[1] = make_float4(-s1 * L2E, -s2 * L2E, c6, 0.f);
    }
}

// ======================= Kernel 2: streaming softmax-attention =============
// grid (NT/32, B), 256 threads. Tt=32 targets/block, context in 128-chunks.

__device__ __forceinline__ float ex2f(float x) {
    float y;
    asm("ex2.approx.ftz.f32 %0, %1;" : "=f"(y) : "f"(x));
    return y;
}

__global__ void __launch_bounds__(256, 2)
attn_kernel(const float* __restrict__ xc, const float* __restrict__ yc,
            float* __restrict__ out) {
    __shared__ float skv[128 * 8];    // chunk key features
    __shared__ float syc[128 * 32];   // chunk values
    __shared__ float sw[128 * 36];    // logits / weights (pad 36), reused for split-reduce
    __shared__ float sq[256];         // 32 targets x 8 query floats
    __shared__ float smx[32], sl[32], ssc[32];
    __shared__ float rmax[256], rsum[256];

    int tid = threadIdx.x;
    int b = blockIdx.y;
    int t0 = blockIdx.x * 32;

    sq[tid] = g_q[(b * NT + t0) * 8 + tid];
    if (tid < 32) { smx[tid] = -1e30f; sl[tid] = 0.f; }
    __syncthreads();

    int tP = tid & 31, cg = tid >> 5;            // P-phase mapping
    float q0 = sq[tP * 8 + 0], q1 = sq[tP * 8 + 1], q2 = sq[tP * 8 + 2];
    float q3 = sq[tP * 8 + 3], q4 = sq[tP * 8 + 4], q5 = sq[tP * 8 + 5];
    float q6 = sq[tP * 8 + 6];

    float acc[4][4];
#pragma unroll
    for (int i = 0; i < 4; ++i)
#pragma unroll
        for (int jj = 0; jj < 4; ++jj) acc[i][jj] = 0.f;

    int s4 = tid >> 6, u = tid & 63, tt = u >> 3, dd = u & 7;  // GEMM mapping

    for (int ch = 0; ch < 8; ++ch) {
        int cbase = ch * 128;
        __syncthreads();   // previous chunk's GEMM reads done before overwrite

        if (tid < 128) {
            const float* xp = &xc[(b * NC + cbase + tid) * 3];
            float x0 = xp[0], x1 = xp[1], x2 = xp[2];
            float4* kv = (float4*)&skv[tid * 8];
            kv[0] = make_float4(x0, x1, x2, x0 * x0);
            kv[1] = make_float4(x1 * x1, x2 * x2, 1.f, 0.f);
        }
        {
            const float4* ys = (const float4*)&yc[(b * NC + cbase) * 32];
            float4* yd = (float4*)syc;
#pragma unroll
            for (int r = 0; r < 4; ++r) yd[tid + 256 * r] = ys[tid + 256 * r];
        }
        __syncthreads();

        // ---- logits (log2 units) + chunk max ----
        float preg[16];
        float lmax = -1e30f;
#pragma unroll
        for (int i = 0; i < 16; ++i) {
            const float4* kv = (const float4*)&skv[(cg * 16 + i) * 8];
            float4 ka = kv[0], kb = kv[1];
            float P = fmaf(q0, ka.x, fmaf(q1, ka.y, fmaf(q2, ka.z,
                      fmaf(q3, ka.w, fmaf(q4, kb.x, fmaf(q5, kb.y, q6))))));
            preg[i] = P;
            lmax = fmaxf(lmax, P);
        }
        rmax[cg * 32 + tP] = lmax;
        __syncthreads();

        if (tid < 32) {
            float m = rmax[tid];
#pragma unroll
            for (int g2 = 1; g2 < 8; ++g2) m = fmaxf(m, rmax[g2 * 32 + tid]);
            float mo = smx[tid], mn = fmaxf(mo, m);
            ssc[tid] = ex2f(mo - mn);
            smx[tid] = mn;
        }
        __syncthreads();

        // rescale accumulators by exp2(m_old - m_new)
#pragma unroll
        for (int i = 0; i < 4; ++i) {
            float sc = ssc[tt * 4 + i];
#pragma unroll
            for (int jj = 0; jj < 4; ++jj) acc[i][jj] *= sc;
        }

        // ---- weights + row sums ----
        {
            float m = smx[tP];
            float lsum = 0.f;
#pragma unroll
            for (int i = 0; i < 16; ++i) {
                float w = ex2f(preg[i] - m);
                lsum += w;
                sw[(cg * 16 + i) * 36 + tP] = w;
            }
            rsum[cg * 32 + tP] = lsum;
        }
        __syncthreads();

        if (tid < 32) {
            float sum = rsum[tid];
#pragma unroll
            for (int g2 = 1; g2 < 8; ++g2) sum += rsum[g2 * 32 + tid];
            sl[tid] = fmaf(sl[tid], ssc[tid], sum);
        }

        // ---- value GEMM: acc[t][d] += w[c][t]*yc[c][d], 4-way c-split ----
#pragma unroll 8
        for (int k = 0; k < 32; ++k) {
            int c = s4 * 32 + k;
            float4 wv = *(const float4*)&sw[c * 36 + tt * 4];
            float4 yv = *(const float4*)&syc[c * 32 + dd * 4];
            acc[0][0] = fmaf(wv.x, yv.x, acc[0][0]); acc[0][1] = fmaf(wv.x, yv.y, acc[0][1]);
            acc[0][2] = fmaf(wv.x, yv.z, acc[0][2]); acc[0][3] = fmaf(wv.x, yv.w, acc[0][3]);
            acc[1][0] = fmaf(wv.y, yv.x, acc[1][0]); acc[1][1] = fmaf(wv.y, yv.y, acc[1][1]);
            acc[1][2] = fmaf(wv.y, yv.z, acc[1][2]); acc[1][3] = fmaf(wv.y, yv.w, acc[1][3]);
            acc[2][0] = fmaf(wv.z, yv.x, acc[2][0]); acc[2][1] = fmaf(wv.z, yv.y, acc[2][1]);
            acc[2][2] = fmaf(wv.z, yv.z, acc[2][2]); acc[2][3] = fmaf(wv.z, yv.w, acc[2][3]);
            acc[3][0] = fmaf(wv.w, yv.x, acc[3][0]); acc[3][1] = fmaf(wv.w, yv.y, acc[3][1]);
            acc[3][2] = fmaf(wv.w, yv.z, acc[3][2]); acc[3][3] = fmaf(wv.w, yv.w, acc[3][3]);
        }
    }
    __syncthreads();

    // ---- reduce the 4 c-splits (reuse sw: 4 x 32 x 32 floats) ----
#pragma unroll
    for (int i = 0; i < 4; ++i)
        *(float4*)&sw[s4 * 1024 + (tt * 4 + i) * 32 + dd * 4] =
            make_float4(acc[i][0], acc[i][1], acc[i][2], acc[i][3]);
    __syncthreads();

    {
        int t = tid >> 3, dg = tid & 7;
        float4 v = make_float4(0.f, 0.f, 0.f, 0.f);
#pragma unroll
        for (int sI = 0; sI < 4; ++sI) {
            float4 a = *(const float4*)&sw[sI * 1024 + t * 32 + dg * 4];
            v.x += a.x; v.y += a.y; v.z += a.z; v.w += a.w;
        }
        float inv = 1.0f / sl[t];
        v.x *= inv; v.y *= inv; v.z *= inv; v.w *= inv;
        *(float4*)&out[(b * NT + t0 + t) * 32 + dg * 4] = v;
    }
}

// ============================== launch =====================================
extern "C" void kernel_launch(void* const* d_in, const int* in_sizes, int n_in,
                              void* d_out, int out_size) {
    (void)in_sizes; (void)n_in; (void)out_size;
    const float* xc = (const float*)d_in[0];
    const float* yc = (const float*)d_in[1];
    const float* xt = (const float*)d_in[2];
    const float* W0 = (const float*)d_in[3];
    const float* b0 = (const float*)d_in[4];
    const float* W1 = (const float*)d_in[5];
    const float* b1 = (const float*)d_in[6];
    const float* W2 = (const float*)d_in[7];
    const float* b2 = (const float*)d_in[8];
    const float* W3 = (const float*)d_in[9];
    const float* b3 = (const float*)d_in[10];
    float* out = (float*)d_out;

    size_t smem1 = SMEM1_FLOATS * sizeof(float);
    cudaFuncSetAttribute(mlp_kernel, cudaFuncAttributeMaxDynamicSharedMemorySize,
                         (int)smem1);

    mlp_kernel<<<256, TPB1, smem1>>>(xt, W0, b0, W1, b1, W2, b2, W3, b3);
    attn_kernel<<<dim3(NT / 32, B_SZ), 256>>>(xc, yc, out);
}

// round 4
// speedup vs baseline: 1.0661x; 1.0661x over previous
#include <cuda_runtime.h>
#include <math.h>

// ---------------------------------------------------------------------------
// B=8, Nc=1024, Nt=1024, Dx=3, Dy=32, H=128
// inputs: xc, yc, xt, W0, b0, W1, b1, W2, b2, W3, b3 (all f32)
// out: (B, Nt, 32) f32
// ---------------------------------------------------------------------------

#define B_SZ 8
#define NC 1024
#define NT 1024

// q[0..2]=2*sig*xt*L2E, q[3..5]=-sig*L2E, q[6]=-(sum sig*xt^2)*L2E
__device__ float g_q[B_SZ * NT * 8];

// ---------------- packed f32x2 helpers (Blackwell FFMA2) -------------------
__device__ __forceinline__ unsigned long long dup2(float x) {
    unsigned long long r;
    asm("mov.b64 %0, {%1, %1};" : "=l"(r) : "f"(x));
    return r;
}
__device__ __forceinline__ void fma2(unsigned long long& d,
                                     unsigned long long a, unsigned long long b) {
    asm("fma.rn.f32x2 %0, %1, %2, %0;" : "+l"(d) : "l"(a), "l"(b));
}
__device__ __forceinline__ unsigned long long mul2(unsigned long long a,
                                                   unsigned long long b) {
    unsigned long long r;
    asm("mul.rn.f32x2 %0, %1, %2;" : "=l"(r) : "l"(a), "l"(b));
    return r;
}
__device__ __forceinline__ unsigned long long add2(unsigned long long a,
                                                   unsigned long long b) {
    unsigned long long r;
    asm("add.rn.f32x2 %0, %1, %2;" : "=l"(r) : "l"(a), "l"(b));
    return r;
}
__device__ __forceinline__ void unpack2(unsigned long long v, float& lo, float& hi) {
    asm("mov.b64 {%0, %1}, %2;" : "=f"(lo), "=f"(hi) : "l"(v));
}
__device__ __forceinline__ float ex2f(float x) {
    float y;
    asm("ex2.approx.ftz.f32 %0, %1;" : "=f"(y) : "f"(x));
    return y;
}

// ======================= Kernel 1: MLP -> sigma -> q =======================
// 256 blocks x 512 threads, 32 points/block. Single 64KB weight buffer
// (W1 then W2) so two blocks fit per SM.

#define TPB1 512
#define oW  0        /* 16384 : W1 then W2 */
#define oW0 16384    /* 384 */
#define oW3 16768    /* 384 */
#define ob0 17152
#define ob1 17280
#define ob2 17408
#define ob3 17536    /* 3, pad 16 */
#define oxt 17552    /* 96 */
#define ohA 17664    /* 4096 */
#define ohB 21760    /* 4096 */
#define oso 25856    /* 96 */
#define SMEM1_FLOATS 25984

__device__ __forceinline__ void cp4(float* dst, const float* src, int n4, int tid) {
    const float4* s4 = (const float4*)src;
    float4* d4 = (float4*)dst;
    for (int i = tid; i < n4; i += TPB1) d4[i] = s4[i];
}

// one hidden layer: thread owns unit j for 8 points of group g, f32x2 math
__device__ __forceinline__ void hidden_layer(float* s, int oin, int oout,
                                             int oWb, int ob, int g, int j) {
    unsigned long long A0 = dup2(s[ob + j]);
    unsigned long long A1 = A0, A2 = A0, A3 = A0;
    const ulonglong2* in2 = (const ulonglong2*)&s[oin + g * 1024];
#pragma unroll 8
    for (int k = 0; k < 128; ++k) {
        ulonglong2 h01 = in2[k * 2];
        ulonglong2 h23 = in2[k * 2 + 1];
        unsigned long long wd = dup2(s[oWb + k * 128 + j]);
        fma2(A0, h01.x, wd);
        fma2(A1, h01.y, wd);
        fma2(A2, h23.x, wd);
        fma2(A3, h23.y, wd);
    }
    float a0, a1, a2, a3, a4, a5, a6, a7;
    unpack2(A0, a0, a1); unpack2(A1, a2, a3);
    unpack2(A2, a4, a5); unpack2(A3, a6, a7);
    float4* od = (float4*)&s[oout + g * 1024 + j * 8];
    od[0] = make_float4(fmaxf(a0, 0.f), fmaxf(a1, 0.f), fmaxf(a2, 0.f), fmaxf(a3, 0.f));
    od[1] = make_float4(fmaxf(a4, 0.f), fmaxf(a5, 0.f), fmaxf(a6, 0.f), fmaxf(a7, 0.f));
}

__global__ void __launch_bounds__(TPB1, 2)
mlp_kernel(const float* __restrict__ xt,
           const float* __restrict__ W0, const float* __restrict__ b0,
           const float* __restrict__ W1, const float* __restrict__ b1,
           const float* __restrict__ W2, const float* __restrict__ b2,
           const float* __restrict__ W3, const float* __restrict__ b3) {
    extern __shared__ float s[];
    int tid = threadIdx.x;
    int g = tid >> 7;        // 4 groups x 8 points
    int j = tid & 127;       // unit

    cp4(&s[oW], W1, 4096, tid);
    cp4(&s[oW0], W0, 96, tid);
    cp4(&s[oW3], W3, 96, tid);
    cp4(&s[ob0], b0, 32, tid);
    cp4(&s[ob1], b1, 32, tid);
    cp4(&s[ob2], b2, 32, tid);
    if (tid < 3) s[ob3 + tid] = b3[tid];

    int pbase = blockIdx.x * 32;
    if (tid < 96) s[oxt + tid] = xt[pbase * 3 + tid];
    __syncthreads();

    // ---- layer 0: 3 -> 128 ----
    {
        float bb = s[ob0 + j];
        float w0 = s[oW0 + j], w1 = s[oW0 + 128 + j], w2 = s[oW0 + 256 + j];
        float a[8];
#pragma unroll
        for (int p = 0; p < 8; ++p) {
            int lp = g * 8 + p;
            float x0 = s[oxt + lp * 3 + 0];
            float x1 = s[oxt + lp * 3 + 1];
            float x2 = s[oxt + lp * 3 + 2];
            a[p] = fmaxf(fmaf(x2, w2, fmaf(x1, w1, fmaf(x0, w0, bb))), 0.f);
        }
        float4* od = (float4*)&s[ohA + g * 1024 + j * 8];
        od[0] = make_float4(a[0], a[1], a[2], a[3]);
        od[1] = make_float4(a[4], a[5], a[6], a[7]);
    }
    __syncthreads();

    hidden_layer(s, ohA, ohB, oW, ob1, g, j);   // layer 1 (W1)
    __syncthreads();
    cp4(&s[oW], W2, 4096, tid);                 // overwrite with W2
    __syncthreads();
    hidden_layer(s, ohB, ohA, oW, ob2, g, j);   // layer 2 (W2)
    __syncthreads();

    // ---- output layer: 128 -> 3 ----
    if (j < 24) {
        int qq = j / 3, d = j - qq * 3;
        float acc = s[ob3 + d];
        const float* hin = &s[ohA + g * 1024];
#pragma unroll 8
        for (int k = 0; k < 128; ++k)
            acc = fmaf(hin[k * 8 + qq], s[oW3 + k * 3 + d], acc);
        s[oso + (g * 8 + qq) * 3 + d] = acc;
    }
    __syncthreads();

    // ---- epilogue: sigma = exp(o), build q ----
    if (tid < 32) {
        int lp = tid;
        float o0 = s[oso + lp * 3 + 0];
        float o1 = s[oso + lp * 3 + 1];
        float o2 = s[oso + lp * 3 + 2];
        float s0 = expf(o0), s1 = expf(o1), s2 = expf(o2);
        float x0 = s[oxt + lp * 3 + 0];
        float x1 = s[oxt + lp * 3 + 1];
        float x2 = s[oxt + lp * 3 + 2];
        const float L2E = 1.44269504088896340736f;
        float c6 = -(s0 * x0 * x0 + s1 * x1 * x1 + s2 * x2 * x2) * L2E;
        float4* qd = (float4*)&g_q[(pbase + lp) * 8];
        qd[0] = make_float4(2.f * s0 * x0 * L2E, 2.f * s1 * x1 * L2E,
                            2.f * s2 * x2 * L2E, -s0 * L2E);
        qd[1] = make_float4(-s1 * L2E, -s2 * L2E, c6, 0.f);
    }
}

// ======================= Kernel 2: streaming softmax-attention =============
// grid (32, 8), 256 threads, 32 targets/block, 128-context chunks.
// Value GEMM: 8 targets x 8 dy per thread, 16-way context split, f32x2.

#define AKV 0        /* 6 x 128 SoA key features */
#define ASYC 1024    /* 128 x 32 values */
#define ASW 5120     /* 128 x 36 weights */
#define ASQ 9728     /* 32 x 8 queries */
#define ASMX 9984
#define ASL 10016
#define ASSC 10048
#define ARMX 10080   /* 256 */
#define ARSM 10336   /* 256 */
#define ARED 1024    /* 8 x 32 x 32 reduce buffer (reuses ASYC/ASW) */
#define ATOT 10592

__global__ void __launch_bounds__(256, 2)
attn_kernel(const float* __restrict__ xc, const float* __restrict__ yc,
            float* __restrict__ out) {
    __shared__ __align__(16) float S[ATOT];

    int tid = threadIdx.x;
    int b = blockIdx.y;
    int t0 = blockIdx.x * 32;

    S[ASQ + tid] = g_q[(b * NT + t0) * 8 + tid];
    if (tid < 32) { S[ASMX + tid] = -1e30f; S[ASL + tid] = 0.f; }
    __syncthreads();

    int tP = tid & 31, cg = tid >> 5;                    // logit mapping
    float q0 = S[ASQ + tP * 8 + 0], q1 = S[ASQ + tP * 8 + 1];
    float q2 = S[ASQ + tP * 8 + 2], q3 = S[ASQ + tP * 8 + 3];
    float q4 = S[ASQ + tP * 8 + 4], q5 = S[ASQ + tP * 8 + 5];
    float q6 = S[ASQ + tP * 8 + 6];

    int s16 = tid >> 4, u = tid & 15, tg = u >> 2, dg = u & 3;  // GEMM mapping

    unsigned long long acc[8][4];
#pragma unroll
    for (int i = 0; i < 8; ++i)
#pragma unroll
        for (int jj = 0; jj < 4; ++jj) acc[i][jj] = 0ull;

    for (int ch = 0; ch < 8; ++ch) {
        int cbase = ch * 128;
        __syncthreads();   // prior GEMM reads done before overwrite

        if (tid < 128) {
            const float* xp = &xc[(b * NC + cbase + tid) * 3];
            float x0 = xp[0], x1 = xp[1], x2 = xp[2];
            S[AKV + tid] = x0;
            S[AKV + 128 + tid] = x1;
            S[AKV + 256 + tid] = x2;
            S[AKV + 384 + tid] = x0 * x0;
            S[AKV + 512 + tid] = x1 * x1;
            S[AKV + 640 + tid] = x2 * x2;
        }
        {
            const float4* ys = (const float4*)&yc[(b * NC + cbase) * 32];
            float4* yd = (float4*)&S[ASYC];
#pragma unroll
            for (int r = 0; r < 4; ++r) yd[tid + 256 * r] = ys[tid + 256 * r];
        }
        __syncthreads();

        // ---- logits (log2 units), paired over contexts ----
        float preg[16];
        float lmax = -1e30f;
        unsigned long long q0d = dup2(q0), q1d = dup2(q1), q2d = dup2(q2);
        unsigned long long q3d = dup2(q3), q4d = dup2(q4), q5d = dup2(q5);
        unsigned long long q6d = dup2(q6);
#pragma unroll
        for (int i4 = 0; i4 < 4; ++i4) {
            int c0 = cg * 16 + i4 * 4;
            ulonglong2 f0 = *(const ulonglong2*)&S[AKV + c0];
            ulonglong2 f1 = *(const ulonglong2*)&S[AKV + 128 + c0];
            ulonglong2 f2 = *(const ulonglong2*)&S[AKV + 256 + c0];
            ulonglong2 f3 = *(const ulonglong2*)&S[AKV + 384 + c0];
            ulonglong2 f4 = *(const ulonglong2*)&S[AKV + 512 + c0];
            ulonglong2 f5 = *(const ulonglong2*)&S[AKV + 640 + c0];
            unsigned long long P01 = q6d, P23 = q6d;
            fma2(P01, f0.x, q0d); fma2(P23, f0.y, q0d);
            fma2(P01, f1.x, q1d); fma2(P23, f1.y, q1d);
            fma2(P01, f2.x, q2d); fma2(P23, f2.y, q2d);
            fma2(P01, f3.x, q3d); fma2(P23, f3.y, q3d);
            fma2(P01, f4.x, q4d); fma2(P23, f4.y, q4d);
            fma2(P01, f5.x, q5d); fma2(P23, f5.y, q5d);
            unpack2(P01, preg[i4 * 4 + 0], preg[i4 * 4 + 1]);
            unpack2(P23, preg[i4 * 4 + 2], preg[i4 * 4 + 3]);
            lmax = fmaxf(lmax, fmaxf(fmaxf(preg[i4 * 4], preg[i4 * 4 + 1]),
                                     fmaxf(preg[i4 * 4 + 2], preg[i4 * 4 + 3])));
        }
        S[ARMX + cg * 32 + tP] = lmax;
        __syncthreads();

        if (tid < 32) {
            float m = S[ARMX + tid];
#pragma unroll
            for (int g2 = 1; g2 < 8; ++g2) m = fmaxf(m, S[ARMX + g2 * 32 + tid]);
            float mo = S[ASMX + tid], mn = fmaxf(mo, m);
            S[ASSC + tid] = ex2f(mo - mn);
            S[ASMX + tid] = mn;
        }
        __syncthreads();

        // rescale accumulators
#pragma unroll
        for (int wi = 0; wi < 8; ++wi) {
            unsigned long long scd = dup2(S[ASSC + tg * 8 + wi]);
#pragma unroll
            for (int dj = 0; dj < 4; ++dj) acc[wi][dj] = mul2(acc[wi][dj], scd);
        }

        // ---- weights + row sums ----
        {
            float m = S[ASMX + tP];
            float lsum = 0.f;
#pragma unroll
            for (int i = 0; i < 16; ++i) {
                float w = ex2f(preg[i] - m);
                lsum += w;
                S[ASW + (cg * 16 + i) * 36 + tP] = w;
            }
            S[ARSM + cg * 32 + tP] = lsum;
        }
        __syncthreads();

        if (tid < 32) {
            float sum = S[ARSM + tid];
#pragma unroll
            for (int g2 = 1; g2 < 8; ++g2) sum += S[ARSM + g2 * 32 + tid];
            S[ASL + tid] = fmaf(S[ASL + tid], S[ASSC + tid], sum);
        }

        // ---- value GEMM: acc[t][dpair] += w[c][t]*y[c][dpair] ----
#pragma unroll
        for (int k = 0; k < 8; ++k) {
            int c = s16 * 8 + k;
            float4 wa = *(const float4*)&S[ASW + c * 36 + tg * 8];
            float4 wb = *(const float4*)&S[ASW + c * 36 + tg * 8 + 4];
            ulonglong2 ya = *(const ulonglong2*)&S[ASYC + c * 32 + dg * 8];
            ulonglong2 yb = *(const ulonglong2*)&S[ASYC + c * 32 + dg * 8 + 4];
            unsigned long long w;
            w = dup2(wa.x);
            fma2(acc[0][0], ya.x, w); fma2(acc[0][1], ya.y, w);
            fma2(acc[0][2], yb.x, w); fma2(acc[0][3], yb.y, w);
            w = dup2(wa.y);
            fma2(acc[1][0], ya.x, w); fma2(acc[1][1], ya.y, w);
            fma2(acc[1][2], yb.x, w); fma2(acc[1][3], yb.y, w);
            w = dup2(wa.z);
            fma2(acc[2][0], ya.x, w); fma2(acc[2][1], ya.y, w);
            fma2(acc[2][2], yb.x, w); fma2(acc[2][3], yb.y, w);
            w = dup2(wa.w);
            fma2(acc[3][0], ya.x, w); fma2(acc[3][1], ya.y, w);
            fma2(acc[3][2], yb.x, w); fma2(acc[3][3], yb.y, w);
            w = dup2(wb.x);
            fma2(acc[4][0], ya.x, w); fma2(acc[4][1], ya.y, w);
            fma2(acc[4][2], yb.x, w); fma2(acc[4][3], yb.y, w);
            w = dup2(wb.y);
            fma2(acc[5][0], ya.x, w); fma2(acc[5][1], ya.y, w);
            fma2(acc[5][2], yb.x, w); fma2(acc[5][3], yb.y, w);
            w = dup2(wb.z);
            fma2(acc[6][0], ya.x, w); fma2(acc[6][1], ya.y, w);
            fma2(acc[6][2], yb.x, w); fma2(acc[6][3], yb.y, w);
            w = dup2(wb.w);
            fma2(acc[7][0], ya.x, w); fma2(acc[7][1], ya.y, w);
            fma2(acc[7][2], yb.x, w); fma2(acc[7][3], yb.y, w);
        }
    }
    __syncthreads();

    // ---- 16-way split reduction (two phases into 8 buffers) ----
    if (s16 < 8) {
#pragma unroll
        for (int wi = 0; wi < 8; ++wi) {
            int t = tg * 8 + wi;
            ulonglong2* dst = (ulonglong2*)&S[ARED + s16 * 1024 + t * 32 + dg * 8];
            ulonglong2 v0; v0.x = acc[wi][0]; v0.y = acc[wi][1];
            ulonglong2 v1; v1.x = acc[wi][2]; v1.y = acc[wi][3];
            dst[0] = v0; dst[1] = v1;
        }
    }
    __syncthreads();
    if (s16 >= 8) {
        int sI = s16 - 8;
#pragma unroll
        for (int wi = 0; wi < 8; ++wi) {
            int t = tg * 8 + wi;
            ulonglong2* p = (ulonglong2*)&S[ARED + sI * 1024 + t * 32 + dg * 8];
            ulonglong2 v0 = p[0], v1 = p[1];
            v0.x = add2(v0.x, acc[wi][0]); v0.y = add2(v0.y, acc[wi][1]);
            v1.x = add2(v1.x, acc[wi][2]); v1.y = add2(v1.y, acc[wi][3]);
            p[0] = v0; p[1] = v1;
        }
    }
    __syncthreads();

    {
        int t = tid >> 3, dq = tid & 7;
        unsigned long long r0 = 0ull, r1 = 0ull;
#pragma unroll
        for (int sI = 0; sI < 8; ++sI) {
            ulonglong2 v = *(const ulonglong2*)&S[ARED + sI * 1024 + t * 32 + dq * 4];
            r0 = add2(r0, v.x);
            r1 = add2(r1, v.y);
        }
        unsigned long long invd = dup2(1.0f / S[ASL + t]);
        r0 = mul2(r0, invd);
        r1 = mul2(r1, invd);
        ulonglong2 o; o.x = r0; o.y = r1;
        *(ulonglong2*)&out[(b * NT + t0 + t) * 32 + dq * 4] = o;
    }
}

// ============================== launch =====================================
extern "C" void kernel_launch(void* const* d_in, const int* in_sizes, int n_in,
                              void* d_out, int out_size) {
    (void)in_sizes; (void)n_in; (void)out_size;
    const float* xc = (const float*)d_in[0];
    const float* yc = (const float*)d_in[1];
    const float* xt = (const float*)d_in[2];
    const float* W0 = (const float*)d_in[3];
    const float* b0 = (const float*)d_in[4];
    const float* W1 = (const float*)d_in[5];
    const float* b1 = (const float*)d_in[6];
    const float* W2 = (const float*)d_in[7];
    const float* b2 = (const float*)d_in[8];
    const float* W3 = (const float*)d_in[9];
    const float* b3 = (const float*)d_in[10];
    float* out = (float*)d_out;

    size_t smem1 = SMEM1_FLOATS * sizeof(float);
    cudaFuncSetAttribute(mlp_kernel, cudaFuncAttributeMaxDynamicSharedMemorySize,
                         (int)smem1);

    mlp_kernel<<<256, TPB1, smem1>>>(xt, W0, b0, W1, b1, W2, b2, W3, b3);
    attn_kernel<<<dim3(NT / 32, B_SZ), 256>>>(xc, yc, out);
}